// round 10
// baseline (speedup 1.0000x reference)
#include <cuda_runtime.h>
#include <stdint.h>

// Graph2Col: stable stream compaction. 3-kernel: count -> scan -> scatter.
// Input : mapping [128, 2048, 32] int32, -1 = empty. total = 8388608.
// Output float32 buffer of 5*total elements:
//   [0, 2*total)        nodes [total,2] : (row, value)      or (-1,-1)
//   [2*total, 5*total)  cols  [total,3] : (row, vert, reg)  or (-1,-1,-1)

#define CHUNK      4096
#define NTHREADS   256
#define NWARPS     (NTHREADS / 32)      // 8
#define WELEMS     (CHUNK / NWARPS)     // 512 elements per warp
#define ITERS      (WELEMS / 32)        // 16
#define MAX_BLOCKS 8192
#define SCAN_T     1024

#define CNT_CHUNK  8192                 // count kernel: 32 elems/thread

__device__ int g_blk_cnt[MAX_BLOCKS];
__device__ int g_blk_off[MAX_BLOCKS + 1];

__global__ void __launch_bounds__(NTHREADS)
count_kernel(const int* __restrict__ map, int total, int sc_blocks) {
    const int blk  = blockIdx.x;
    const int base = blk * CNT_CHUNK + threadIdx.x * 32;
    int c = 0;
    if (base + 32 <= total) {
        const int4* p4 = reinterpret_cast<const int4*>(map + base);
        int4 r[8];
        #pragma unroll
        for (int k = 0; k < 8; k++) r[k] = p4[k];      // 8 loads in flight
        #pragma unroll
        for (int k = 0; k < 8; k++)
            c += (r[k].x != -1) + (r[k].y != -1) + (r[k].z != -1) + (r[k].w != -1);
    } else {
        for (int j = 0; j < 32; j++) {
            int i = base + j;
            if (i < total) c += (map[i] != -1);
        }
    }
    #pragma unroll
    for (int o = 16; o; o >>= 1) c += __shfl_down_sync(0xffffffffu, c, o);
    __shared__ int ws[NWARPS];
    if ((threadIdx.x & 31) == 0) ws[threadIdx.x >> 5] = c;
    __syncthreads();
    if (threadIdx.x < 2) {
        // each count block covers 2 scatter chunks; publish per-scatter-chunk counts
        int s = 0;
        #pragma unroll
        for (int w = 0; w < NWARPS / 2; w++) s += ws[threadIdx.x * (NWARPS / 2) + w];
        const int sc = blk * 2 + threadIdx.x;
        if (sc < sc_blocks) g_blk_cnt[sc] = s;
    }
}

__global__ void __launch_bounds__(SCAN_T)
scan_kernel(int nblocks) {
    __shared__ int buf[2][SCAN_T];
    const int t = threadIdx.x;
    const int i0 = 2 * t, i1 = 2 * t + 1;
    const int a = (i0 < nblocks) ? g_blk_cnt[i0] : 0;
    const int b = (i1 < nblocks) ? g_blk_cnt[i1] : 0;
    const int s = a + b;
    int cur = 0;
    buf[0][t] = s;
    __syncthreads();
    #pragma unroll
    for (int o = 1; o < SCAN_T; o <<= 1) {
        int v = buf[cur][t];
        if (t >= o) v += buf[cur][t - o];
        buf[cur ^ 1][t] = v;
        cur ^= 1;
        __syncthreads();
    }
    const int incl = buf[cur][t];
    const int excl = incl - s;
    if (i0 < nblocks) g_blk_off[i0] = excl;
    if (i1 < nblocks) g_blk_off[i1] = excl + a;
    if (t == SCAN_T - 1) g_blk_off[nblocks] = incl;   // n_valid
}

// LAYOUT 0: float32 (confirmed). 1: int64. 2: int32 nodes + int64 cols.
template <int LAYOUT>
__global__ void __launch_bounds__(NTHREADS)
scatter_kernel(const int* __restrict__ map, void* __restrict__ outv,
               int total, int nblocks) {
    const int blk  = blockIdx.x;
    const int tid  = threadIdx.x;
    const int lane = tid & 31;
    const int wid  = tid >> 5;
    const int wElemBase = blk * CHUNK + wid * WELEMS;
    const unsigned below = (1u << lane) - 1u;

    // warp-strided loads: lane handles wElemBase + 32k + lane
    int vals[ITERS];
    unsigned masks[ITERS];
    int c = 0;
    #pragma unroll
    for (int k = 0; k < ITERS; k++) {
        const int i = wElemBase + 32 * k + lane;
        vals[k] = (i < total) ? __ldg(map + i) : -1;
        const bool ok = (i < total) && (vals[k] != -1);
        masks[k] = __ballot_sync(0xffffffffu, ok);
        c += __popc(masks[k]);   // warp-uniform
    }

    __shared__ int wsum[NWARPS];
    if (lane == 0) wsum[wid] = c;
    __syncthreads();
    int wpref = 0;
    #pragma unroll
    for (int w = 0; w < NWARPS; w++) wpref += (w < wid) ? wsum[w] : 0;

    const int nvalid = g_blk_off[nblocks];
    int wbase = g_blk_off[blk] + wpref;

    float* const outF  = (float*)outv;
    float* const colsF = outF + 2LL * (long long)total;

    #pragma unroll
    for (int k = 0; k < ITERS; k++) {
        const int ibase = wElemBase + 32 * k;    // multiple of 32
        const unsigned m = masks[k];

        if (LAYOUT == 0 && m == 0xffffffffu) {
            // FAST PATH: dense 32-aligned block => row/vert warp-uniform.
            const float rowF  = (float)(ibase >> 16);
            const float vertF = (float)((ibase >> 5) & 2047);
            {
                float2 n2;
                n2.x = rowF;
                n2.y = (float)vals[k];
                reinterpret_cast<float2*>(outF)[wbase + lane] = n2;
            }
            const int cb = 3 * wbase;
            #pragma unroll
            for (int s = 0; s < 3; s++) {
                const int j    = s * 32 + lane;          // 0..95
                const int e    = (j * 21846) >> 16;      // j / 3
                const int comp = j - 3 * e;              // j % 3
                const float cv = (comp == 0) ? rowF
                               : (comp == 1) ? vertF
                                             : (float)e; // reg = e for aligned block
                colsF[cb + j] = cv;
            }
            wbase += 32;
            continue;
        }

        // SLOW PATH (rare): per-element, destinations still mostly consecutive.
        const int i     = ibase + lane;
        const int rank  = __popc(m & below);
        const int pexcl = wbase + rank;
        const bool ok   = (m >> lane) & 1u;
        if (i < total) {
            const int q    = ok ? pexcl : (nvalid + (i - pexcl));
            const int row  = i >> 16;
            const int vert = (i >> 5) & 2047;
            const int reg  = i & 31;
            const int v    = vals[k];
            if (LAYOUT == 0) {
                float2 n2;
                n2.x = ok ? (float)row : -1.0f;
                n2.y = ok ? (float)v   : -1.0f;
                reinterpret_cast<float2*>(outF)[q] = n2;
                float* cp = colsF + 3LL * q;
                cp[0] = ok ? (float)row  : -1.0f;
                cp[1] = ok ? (float)vert : -1.0f;
                cp[2] = ok ? (float)reg  : -1.0f;
            } else if (LAYOUT == 1) {
                long long* out  = (long long*)outv;
                long long* cols = out + 2LL * (long long)total;
                longlong2 n2;
                n2.x = ok ? (long long)row : -1LL;
                n2.y = ok ? (long long)v   : -1LL;
                reinterpret_cast<longlong2*>(out)[q] = n2;
                long long* cp = cols + 3LL * q;
                cp[0] = ok ? (long long)row  : -1LL;
                cp[1] = ok ? (long long)vert : -1LL;
                cp[2] = ok ? (long long)reg  : -1LL;
            } else {
                int* out = (int*)outv;
                int2 n2;
                n2.x = ok ? row : -1;
                n2.y = ok ? v   : -1;
                reinterpret_cast<int2*>(out)[q] = n2;
                long long* cols = (long long*)((char*)outv + 8LL * (long long)total);
                long long* cp = cols + 3LL * q;
                cp[0] = ok ? (long long)row  : -1LL;
                cp[1] = ok ? (long long)vert : -1LL;
                cp[2] = ok ? (long long)reg  : -1LL;
            }
        }
        wbase += __popc(m);
    }
}

extern "C" void kernel_launch(void* const* d_in, const int* in_sizes, int n_in,
                              void* d_out, int out_size) {
    const int* map        = (const int*)d_in[0];
    const int  total      = in_sizes[0];                      // 8388608
    const int  nblocks    = (total + CHUNK - 1) / CHUNK;      // 2048 scatter chunks
    const int  cnt_blocks = (total + CNT_CHUNK - 1) / CNT_CHUNK;  // 1024

    count_kernel<<<cnt_blocks, NTHREADS>>>(map, total, nblocks);
    scan_kernel <<<1, SCAN_T>>>(nblocks);

    const long long T = total;
    if ((long long)out_size == 5 * T) {
        scatter_kernel<0><<<nblocks, NTHREADS>>>(map, d_out, total, nblocks);
    } else if ((long long)out_size == 8 * T) {
        scatter_kernel<2><<<nblocks, NTHREADS>>>(map, d_out, total, nblocks);
    } else {
        scatter_kernel<1><<<nblocks, NTHREADS>>>(map, d_out, total, nblocks);
    }
}

// round 11
// speedup vs baseline: 1.1760x; 1.1760x over previous
#include <cuda_runtime.h>
#include <stdint.h>

// Graph2Col: stable stream compaction. 3-kernel: count -> scan -> scatter.
// Input : mapping [128, 2048, 32] int32, -1 = empty. total = 8388608.
// Output float32 buffer of 5*total elements:
//   [0, 2*total)        nodes [total,2] : (row, value)      or (-1,-1)
//   [2*total, 5*total)  cols  [total,3] : (row, vert, reg)  or (-1,-1,-1)

#define CHUNK      4096
#define NTHREADS   256
#define NWARPS     (NTHREADS / 32)      // 8
#define WELEMS     (CHUNK / NWARPS)     // 512 elements per warp
#define ITERS      (WELEMS / 32)        // 16
#define MAX_BLOCKS 8192
#define SCAN_T     1024

__device__ int g_blk_cnt[MAX_BLOCKS];
__device__ int g_blk_off[MAX_BLOCKS + 1];

__global__ void __launch_bounds__(NTHREADS)
count_kernel(const int* __restrict__ map, int total) {
    const int blk  = blockIdx.x;
    const int lane = threadIdx.x & 31;
    const int wid  = threadIdx.x >> 5;
    const int wElemBase = blk * CHUNK + wid * WELEMS;
    int c = 0;
    if (wElemBase + WELEMS <= total) {
        // dense warp-strided int4: each LDG.128 covers 512 contiguous bytes
        const int4* p4 = reinterpret_cast<const int4*>(map) + (wElemBase >> 2);
        int4 r[4];
        #pragma unroll
        for (int k = 0; k < 4; k++) r[k] = __ldg(p4 + 32 * k + lane);
        #pragma unroll
        for (int k = 0; k < 4; k++)
            c += (r[k].x != -1) + (r[k].y != -1) + (r[k].z != -1) + (r[k].w != -1);
    } else {
        for (int k = 0; k < ITERS; k++) {
            const int i = wElemBase + 32 * k + lane;
            if (i < total) c += (__ldg(map + i) != -1);
        }
    }
    #pragma unroll
    for (int o = 16; o; o >>= 1) c += __shfl_down_sync(0xffffffffu, c, o);
    __shared__ int ws[NWARPS];
    if (lane == 0) ws[wid] = c;
    __syncthreads();
    if (threadIdx.x == 0) {
        int s = 0;
        #pragma unroll
        for (int w = 0; w < NWARPS; w++) s += ws[w];
        g_blk_cnt[blk] = s;
    }
}

__global__ void __launch_bounds__(SCAN_T)
scan_kernel(int nblocks) {
    __shared__ int buf[2][SCAN_T];
    const int t = threadIdx.x;
    const int i0 = 2 * t, i1 = 2 * t + 1;
    const int a = (i0 < nblocks) ? g_blk_cnt[i0] : 0;
    const int b = (i1 < nblocks) ? g_blk_cnt[i1] : 0;
    const int s = a + b;
    int cur = 0;
    buf[0][t] = s;
    __syncthreads();
    #pragma unroll
    for (int o = 1; o < SCAN_T; o <<= 1) {
        int v = buf[cur][t];
        if (t >= o) v += buf[cur][t - o];
        buf[cur ^ 1][t] = v;
        cur ^= 1;
        __syncthreads();
    }
    const int incl = buf[cur][t];
    const int excl = incl - s;
    if (i0 < nblocks) g_blk_off[i0] = excl;
    if (i1 < nblocks) g_blk_off[i1] = excl + a;
    if (t == SCAN_T - 1) g_blk_off[nblocks] = incl;   // n_valid
}

// LAYOUT 0: float32 (confirmed). 1: int64. 2: int32 nodes + int64 cols.
template <int LAYOUT>
__global__ void __launch_bounds__(NTHREADS)
scatter_kernel(const int* __restrict__ map, void* __restrict__ outv,
               int total, int nblocks) {
    const int blk  = blockIdx.x;
    const int tid  = threadIdx.x;
    const int lane = tid & 31;
    const int wid  = tid >> 5;
    const int wElemBase = blk * CHUNK + wid * WELEMS;
    const unsigned below = (1u << lane) - 1u;

    // warp-strided loads: lane handles wElemBase + 32k + lane (dense 128B/instr)
    int vals[ITERS];
    unsigned masks[ITERS];
    int c = 0;
    unsigned allAnd = 0xffffffffu;
    #pragma unroll
    for (int k = 0; k < ITERS; k++) {
        const int i = wElemBase + 32 * k + lane;
        vals[k] = (i < total) ? __ldg(map + i) : -1;
        const bool ok = (i < total) && (vals[k] != -1);
        masks[k] = __ballot_sync(0xffffffffu, ok);
        allAnd &= masks[k];
        c += __popc(masks[k]);   // warp-uniform
    }

    __shared__ int wsum[NWARPS];
    if (lane == 0) wsum[wid] = c;
    __syncthreads();
    int wpref = 0;
    #pragma unroll
    for (int w = 0; w < NWARPS; w++) wpref += (w < wid) ? wsum[w] : 0;

    const int nvalid = g_blk_off[nblocks];
    int wbase = g_blk_off[blk] + wpref;

    float* const outF  = (float*)outv;
    float* const colsF = outF + 2LL * (long long)total;

    if (LAYOUT == 0 && allAnd == 0xffffffffu && wElemBase + WELEMS <= total) {
        // ===== DENSE WHOLE-WARP PATH (~78% of warps): branchless, coalesced =====
        // 512-aligned, 512-long range: row warp-constant, vert = vbase + k.
        const float rowF  = (float)(wElemBase >> 16);
        const int   vbase = (wElemBase >> 5) & 2047;
        // per-lane constants for the cols stream (j = s*32 + lane)
        int   e_[3], comp_[3];
        float eF_[3];
        #pragma unroll
        for (int s = 0; s < 3; s++) {
            const int j = s * 32 + lane;
            e_[s]    = (j * 21846) >> 16;      // j / 3
            comp_[s] = j - 3 * e_[s];          // j % 3
            eF_[s]   = (float)e_[s];           // reg value (aligned block => reg = e)
        }
        #pragma unroll
        for (int k = 0; k < ITERS; k++) {
            const int qb = wbase + 32 * k;
            // nodes: one coalesced STG.64 run per iteration
            float2 n2;
            n2.x = rowF;
            n2.y = (float)vals[k];
            reinterpret_cast<float2*>(outF)[qb + lane] = n2;
            // cols: 96 contiguous floats, 3 dense STG.32 per iteration
            const float vertF = (float)(vbase + k);
            const int   cb    = 3 * qb;
            #pragma unroll
            for (int s = 0; s < 3; s++) {
                const float cv = (comp_[s] == 0) ? rowF
                               : (comp_[s] == 1) ? vertF
                                                 : eF_[s];
                colsF[cb + s * 32 + lane] = cv;
            }
        }
        return;   // this warp is done
    }

    // ===== SPARSE PATH (exact R4 per-element code) =====
    #pragma unroll
    for (int k = 0; k < ITERS; k++) {
        const int i     = wElemBase + 32 * k + lane;
        const unsigned m = masks[k];
        const int rank  = __popc(m & below);
        const int pexcl = wbase + rank;
        const bool ok   = (m >> lane) & 1u;
        if (i < total) {
            const int q    = ok ? pexcl : (nvalid + (i - pexcl));
            const int row  = i >> 16;
            const int vert = (i >> 5) & 2047;
            const int reg  = i & 31;
            const int v    = vals[k];
            if (LAYOUT == 0) {
                float2 n2;
                n2.x = ok ? (float)row : -1.0f;
                n2.y = ok ? (float)v   : -1.0f;
                reinterpret_cast<float2*>(outF)[q] = n2;
                float* cp = colsF + 3LL * q;
                cp[0] = ok ? (float)row  : -1.0f;
                cp[1] = ok ? (float)vert : -1.0f;
                cp[2] = ok ? (float)reg  : -1.0f;
            } else if (LAYOUT == 1) {
                long long* out  = (long long*)outv;
                long long* cols = out + 2LL * (long long)total;
                longlong2 n2;
                n2.x = ok ? (long long)row : -1LL;
                n2.y = ok ? (long long)v   : -1LL;
                reinterpret_cast<longlong2*>(out)[q] = n2;
                long long* cp = cols + 3LL * q;
                cp[0] = ok ? (long long)row  : -1LL;
                cp[1] = ok ? (long long)vert : -1LL;
                cp[2] = ok ? (long long)reg  : -1LL;
            } else {
                int* out = (int*)outv;
                int2 n2;
                n2.x = ok ? row : -1;
                n2.y = ok ? v   : -1;
                reinterpret_cast<int2*>(out)[q] = n2;
                long long* cols = (long long*)((char*)outv + 8LL * (long long)total);
                long long* cp = cols + 3LL * q;
                cp[0] = ok ? (long long)row  : -1LL;
                cp[1] = ok ? (long long)vert : -1LL;
                cp[2] = ok ? (long long)reg  : -1LL;
            }
        }
        wbase += __popc(m);
    }
}

extern "C" void kernel_launch(void* const* d_in, const int* in_sizes, int n_in,
                              void* d_out, int out_size) {
    const int* map     = (const int*)d_in[0];
    const int  total   = in_sizes[0];                 // 8388608
    const int  nblocks = (total + CHUNK - 1) / CHUNK; // 2048

    count_kernel<<<nblocks, NTHREADS>>>(map, total);
    scan_kernel <<<1, SCAN_T>>>(nblocks);

    const long long T = total;
    if ((long long)out_size == 5 * T) {
        scatter_kernel<0><<<nblocks, NTHREADS>>>(map, d_out, total, nblocks);
    } else if ((long long)out_size == 8 * T) {
        scatter_kernel<2><<<nblocks, NTHREADS>>>(map, d_out, total, nblocks);
    } else {
        scatter_kernel<1><<<nblocks, NTHREADS>>>(map, d_out, total, nblocks);
    }
}

// round 12
// speedup vs baseline: 1.1922x; 1.0137x over previous
#include <cuda_runtime.h>
#include <stdint.h>

// Graph2Col: stable stream compaction. 2-kernel: count -> scatter(+inline scan).
// Input : mapping [128, 2048, 32] int32, -1 = empty. total = 8388608.
// Output float32 buffer of 5*total elements:
//   [0, 2*total)        nodes [total,2] : (row, value)      or (-1,-1)
//   [2*total, 5*total)  cols  [total,3] : (row, vert, reg)  or (-1,-1,-1)

#define CHUNK      8192
#define SC_THREADS 512
#define SC_WARPS   (SC_THREADS / 32)    // 16
#define WELEMS     (CHUNK / SC_WARPS)   // 512 elements per scatter warp
#define ITERS      (WELEMS / 32)        // 16

#define CNT_THREADS 256
#define CNT_WARPS   (CNT_THREADS / 32)  // 8
#define CNT_WELEMS  (CHUNK / CNT_WARPS) // 1024 elems/warp -> 8 int4 per lane

#define MAX_BLOCKS 8192

__device__ int g_blk_cnt[MAX_BLOCKS];

__global__ void __launch_bounds__(CNT_THREADS)
count_kernel(const int* __restrict__ map, int total) {
    const int blk  = blockIdx.x;
    const int lane = threadIdx.x & 31;
    const int wid  = threadIdx.x >> 5;
    const int wElemBase = blk * CHUNK + wid * CNT_WELEMS;
    int c = 0;
    if (wElemBase + CNT_WELEMS <= total) {
        // dense warp-strided int4: 8 LDG.128 in flight, each covering 512 B
        const int4* p4 = reinterpret_cast<const int4*>(map) + (wElemBase >> 2);
        int4 r[8];
        #pragma unroll
        for (int k = 0; k < 8; k++) r[k] = __ldg(p4 + 32 * k + lane);
        #pragma unroll
        for (int k = 0; k < 8; k++)
            c += (r[k].x != -1) + (r[k].y != -1) + (r[k].z != -1) + (r[k].w != -1);
    } else {
        for (int k = 0; k < CNT_WELEMS / 32; k++) {
            const int i = wElemBase + 32 * k + lane;
            if (i < total) c += (__ldg(map + i) != -1);
        }
    }
    #pragma unroll
    for (int o = 16; o; o >>= 1) c += __shfl_down_sync(0xffffffffu, c, o);
    __shared__ int ws[CNT_WARPS];
    if (lane == 0) ws[wid] = c;
    __syncthreads();
    if (threadIdx.x == 0) {
        int s = 0;
        #pragma unroll
        for (int w = 0; w < CNT_WARPS; w++) s += ws[w];
        g_blk_cnt[blk] = s;
    }
}

// LAYOUT 0: float32 (confirmed). 1: int64. 2: int32 nodes + int64 cols.
template <int LAYOUT>
__global__ void __launch_bounds__(SC_THREADS)
scatter_kernel(const int* __restrict__ map, void* __restrict__ outv,
               int total, int nblocks) {
    const int blk  = blockIdx.x;
    const int tid  = threadIdx.x;
    const int lane = tid & 31;
    const int wid  = tid >> 5;
    const int wElemBase = blk * CHUNK + wid * WELEMS;
    const unsigned below = (1u << lane) - 1u;

    // ---- warp-strided map loads (dense 128B per LDG) ----
    int vals[ITERS];
    unsigned masks[ITERS];
    int c = 0;
    unsigned allAnd = 0xffffffffu;
    #pragma unroll
    for (int k = 0; k < ITERS; k++) {
        const int i = wElemBase + 32 * k + lane;
        vals[k] = (i < total) ? __ldg(map + i) : -1;
        const bool ok = (i < total) && (vals[k] != -1);
        masks[k] = __ballot_sync(0xffffffffu, ok);
        allAnd &= masks[k];
        c += __popc(masks[k]);   // warp-uniform
    }

    // ---- inline scan: per-block excl prefix + grand total from g_blk_cnt ----
    // nblocks <= 2*SC_THREADS: each thread owns 2 counts.
    int exclPart = 0, totPart = 0;
    {
        const int j0 = 2 * tid, j1 = 2 * tid + 1;
        const int c0 = (j0 < nblocks) ? g_blk_cnt[j0] : 0;
        const int c1 = (j1 < nblocks) ? g_blk_cnt[j1] : 0;
        exclPart = ((j0 < blk) ? c0 : 0) + ((j1 < blk) ? c1 : 0);
        totPart  = c0 + c1;
    }
    #pragma unroll
    for (int o = 16; o; o >>= 1) {
        exclPart += __shfl_down_sync(0xffffffffu, exclPart, o);
        totPart  += __shfl_down_sync(0xffffffffu, totPart,  o);
    }

    __shared__ int wsum[SC_WARPS];
    __shared__ int s_ex[SC_WARPS];
    __shared__ int s_to[SC_WARPS];
    if (lane == 0) { wsum[wid] = c; s_ex[wid] = exclPart; s_to[wid] = totPart; }
    __syncthreads();

    int wpref = 0, excl = 0, nvalid = 0;
    #pragma unroll
    for (int w = 0; w < SC_WARPS; w++) {
        wpref  += (w < wid) ? wsum[w] : 0;
        excl   += s_ex[w];
        nvalid += s_to[w];
    }
    int wbase = excl + wpref;

    float* const outF  = (float*)outv;
    float* const colsF = outF + 2LL * (long long)total;

    if (LAYOUT == 0 && allAnd == 0xffffffffu && wElemBase + WELEMS <= total) {
        // ===== DENSE WHOLE-WARP PATH (~78%): branchless, coalesced =====
        const float rowF  = (float)(wElemBase >> 16);
        const int   vbase = (wElemBase >> 5) & 2047;
        int   comp_[3];
        float eF_[3];
        #pragma unroll
        for (int s = 0; s < 3; s++) {
            const int j = s * 32 + lane;
            const int e = (j * 21846) >> 16;   // j / 3
            comp_[s] = j - 3 * e;              // j % 3
            eF_[s]   = (float)e;               // reg = e for 32-aligned block
        }
        #pragma unroll
        for (int k = 0; k < ITERS; k++) {
            const int qb = wbase + 32 * k;
            float2 n2;
            n2.x = rowF;
            n2.y = (float)vals[k];
            reinterpret_cast<float2*>(outF)[qb + lane] = n2;
            const float vertF = (float)(vbase + k);
            const int   cb    = 3 * qb;
            #pragma unroll
            for (int s = 0; s < 3; s++) {
                const float cv = (comp_[s] == 0) ? rowF
                               : (comp_[s] == 1) ? vertF
                                                 : eF_[s];
                colsF[cb + s * 32 + lane] = cv;
            }
        }
        return;
    }

    // ===== SPARSE PATH =====
    #pragma unroll
    for (int k = 0; k < ITERS; k++) {
        const int i     = wElemBase + 32 * k + lane;
        const unsigned m = masks[k];
        const int rank  = __popc(m & below);
        const int pexcl = wbase + rank;
        const bool ok   = (m >> lane) & 1u;
        if (i < total) {
            const int q    = ok ? pexcl : (nvalid + (i - pexcl));
            const int row  = i >> 16;
            const int vert = (i >> 5) & 2047;
            const int reg  = i & 31;
            const int v    = vals[k];
            if (LAYOUT == 0) {
                float2 n2;
                n2.x = ok ? (float)row : -1.0f;
                n2.y = ok ? (float)v   : -1.0f;
                reinterpret_cast<float2*>(outF)[q] = n2;
                float* cp = colsF + 3LL * q;
                cp[0] = ok ? (float)row  : -1.0f;
                cp[1] = ok ? (float)vert : -1.0f;
                cp[2] = ok ? (float)reg  : -1.0f;
            } else if (LAYOUT == 1) {
                long long* out  = (long long*)outv;
                long long* cols = out + 2LL * (long long)total;
                longlong2 n2;
                n2.x = ok ? (long long)row : -1LL;
                n2.y = ok ? (long long)v   : -1LL;
                reinterpret_cast<longlong2*>(out)[q] = n2;
                long long* cp = cols + 3LL * q;
                cp[0] = ok ? (long long)row  : -1LL;
                cp[1] = ok ? (long long)vert : -1LL;
                cp[2] = ok ? (long long)reg  : -1LL;
            } else {
                int* out = (int*)outv;
                int2 n2;
                n2.x = ok ? row : -1;
                n2.y = ok ? v   : -1;
                reinterpret_cast<int2*>(out)[q] = n2;
                long long* cols = (long long*)((char*)outv + 8LL * (long long)total);
                long long* cp = cols + 3LL * q;
                cp[0] = ok ? (long long)row  : -1LL;
                cp[1] = ok ? (long long)vert : -1LL;
                cp[2] = ok ? (long long)reg  : -1LL;
            }
        }
        wbase += __popc(m);
    }
}

extern "C" void kernel_launch(void* const* d_in, const int* in_sizes, int n_in,
                              void* d_out, int out_size) {
    const int* map     = (const int*)d_in[0];
    const int  total   = in_sizes[0];                 // 8388608
    const int  nblocks = (total + CHUNK - 1) / CHUNK; // 1024

    count_kernel<<<nblocks, CNT_THREADS>>>(map, total);

    const long long T = total;
    if ((long long)out_size == 5 * T) {
        scatter_kernel<0><<<nblocks, SC_THREADS>>>(map, d_out, total, nblocks);
    } else if ((long long)out_size == 8 * T) {
        scatter_kernel<2><<<nblocks, SC_THREADS>>>(map, d_out, total, nblocks);
    } else {
        scatter_kernel<1><<<nblocks, SC_THREADS>>>(map, d_out, total, nblocks);
    }
}

// round 14
// speedup vs baseline: 1.3551x; 1.1367x over previous
#include <cuda_runtime.h>
#include <stdint.h>

// Graph2Col: stable stream compaction. 2-kernel: count -> scatter(+inline scan).
// Input : mapping [128, 2048, 32] int32, -1 = empty. total = 8388608.
// Output float32 buffer of 5*total elements:
//   [0, 2*total)        nodes [total,2] : (row, value)      or (-1,-1)
//   [2*total, 5*total)  cols  [total,3] : (row, vert, reg)  or (-1,-1,-1)

#define CHUNK      4096                  // scatter tile
#define SC_THREADS 256
#define SC_WARPS   (SC_THREADS / 32)     // 8
#define WELEMS     (CHUNK / SC_WARPS)    // 512 elements per scatter warp
#define ITERS      (WELEMS / 32)         // 16

#define CNT_CHUNK   8192                 // count tile (2 scatter tiles)
#define CNT_THREADS 256
#define CNT_WARPS   (CNT_THREADS / 32)   // 8
#define CNT_WELEMS  (CNT_CHUNK / CNT_WARPS) // 1024 elems/warp -> 8 int4/lane

#define MAX_BLOCKS 8192

__device__ int g_blk_cnt[MAX_BLOCKS];

__global__ void __launch_bounds__(CNT_THREADS)
count_kernel(const int* __restrict__ map, int total, int sc_blocks) {
    const int blk  = blockIdx.x;
    const int lane = threadIdx.x & 31;
    const int wid  = threadIdx.x >> 5;
    const int wElemBase = blk * CNT_CHUNK + wid * CNT_WELEMS;
    int c = 0;
    if (wElemBase + CNT_WELEMS <= total) {
        const int4* p4 = reinterpret_cast<const int4*>(map) + (wElemBase >> 2);
        int4 r[8];
        #pragma unroll
        for (int k = 0; k < 8; k++) r[k] = __ldg(p4 + 32 * k + lane);
        #pragma unroll
        for (int k = 0; k < 8; k++)
            c += (r[k].x != -1) + (r[k].y != -1) + (r[k].z != -1) + (r[k].w != -1);
    } else {
        for (int k = 0; k < CNT_WELEMS / 32; k++) {
            const int i = wElemBase + 32 * k + lane;
            if (i < total) c += (__ldg(map + i) != -1);
        }
    }
    #pragma unroll
    for (int o = 16; o; o >>= 1) c += __shfl_down_sync(0xffffffffu, c, o);
    __shared__ int ws[CNT_WARPS];
    if (lane == 0) ws[wid] = c;
    __syncthreads();
    // publish two 4096-chunk sub-counts: warps 0-3 and warps 4-7
    if (threadIdx.x < 2) {
        int s = 0;
        #pragma unroll
        for (int w = 0; w < 4; w++) s += ws[threadIdx.x * 4 + w];
        const int sc = blk * 2 + threadIdx.x;
        if (sc < sc_blocks) g_blk_cnt[sc] = s;
    }
}

// LAYOUT 0: float32 (confirmed). 1: int64. 2: int32 nodes + int64 cols.
template <int LAYOUT>
__global__ void __launch_bounds__(SC_THREADS)
scatter_kernel(const int* __restrict__ map, void* __restrict__ outv,
               int total, int nblocks) {
    const int blk  = blockIdx.x;
    const int tid  = threadIdx.x;
    const int lane = tid & 31;
    const int wid  = tid >> 5;
    const int wElemBase = blk * CHUNK + wid * WELEMS;
    const unsigned below = (1u << lane) - 1u;

    // ---- warp-strided map loads (dense 128B per LDG) ----
    int vals[ITERS];
    unsigned masks[ITERS];
    int c = 0;
    unsigned allAnd = 0xffffffffu;
    #pragma unroll
    for (int k = 0; k < ITERS; k++) {
        const int i = wElemBase + 32 * k + lane;
        vals[k] = (i < total) ? __ldg(map + i) : -1;
        const bool ok = (i < total) && (vals[k] != -1);
        masks[k] = __ballot_sync(0xffffffffu, ok);
        allAnd &= masks[k];
        c += __popc(masks[k]);   // warp-uniform
    }

    // ---- inline scan: per-block excl prefix + grand total over g_blk_cnt ----
    // nblocks <= 8*SC_THREADS; each thread owns 8 counts via two int4 loads.
    int exclPart = 0, totPart = 0;
    {
        const int j = tid * 8;
        if (j + 8 <= nblocks) {
            const int4 a = __ldg(reinterpret_cast<const int4*>(g_blk_cnt + j));
            const int4 b = __ldg(reinterpret_cast<const int4*>(g_blk_cnt + j + 4));
            totPart = a.x + a.y + a.z + a.w + b.x + b.y + b.z + b.w;
            if (j + 8 <= blk) {
                exclPart = totPart;
            } else if (j < blk) {
                exclPart  = (j + 0 < blk) ? a.x : 0;
                exclPart += (j + 1 < blk) ? a.y : 0;
                exclPart += (j + 2 < blk) ? a.z : 0;
                exclPart += (j + 3 < blk) ? a.w : 0;
                exclPart += (j + 4 < blk) ? b.x : 0;
                exclPart += (j + 5 < blk) ? b.y : 0;
                exclPart += (j + 6 < blk) ? b.z : 0;
                exclPart += (j + 7 < blk) ? b.w : 0;
            }
        } else {
            for (int u = 0; u < 8; u++) {
                const int jj = j + u;
                const int cv = (jj < nblocks) ? g_blk_cnt[jj] : 0;
                totPart += cv;
                exclPart += (jj < blk) ? cv : 0;
            }
        }
    }
    #pragma unroll
    for (int o = 16; o; o >>= 1) {
        exclPart += __shfl_down_sync(0xffffffffu, exclPart, o);
        totPart  += __shfl_down_sync(0xffffffffu, totPart,  o);
    }

    __shared__ int wsum[SC_WARPS];
    __shared__ int s_ex[SC_WARPS];
    __shared__ int s_to[SC_WARPS];
    if (lane == 0) { wsum[wid] = c; s_ex[wid] = exclPart; s_to[wid] = totPart; }
    __syncthreads();

    int wpref = 0, excl = 0, nvalid = 0;
    #pragma unroll
    for (int w = 0; w < SC_WARPS; w++) {
        wpref  += (w < wid) ? wsum[w] : 0;
        excl   += s_ex[w];
        nvalid += s_to[w];
    }
    int wbase = excl + wpref;

    float* const outF  = (float*)outv;
    float* const colsF = outF + 2LL * (long long)total;

    if (LAYOUT == 0 && allAnd == 0xffffffffu && wElemBase + WELEMS <= total) {
        // ===== DENSE WHOLE-WARP PATH (~78%): branchless, coalesced =====
        const float rowF  = (float)(wElemBase >> 16);
        const int   vbase = (wElemBase >> 5) & 2047;
        int   comp_[3];
        float eF_[3];
        #pragma unroll
        for (int s = 0; s < 3; s++) {
            const int j = s * 32 + lane;
            const int e = (j * 21846) >> 16;   // j / 3
            comp_[s] = j - 3 * e;              // j % 3
            eF_[s]   = (float)e;               // reg = e for 32-aligned block
        }
        #pragma unroll
        for (int k = 0; k < ITERS; k++) {
            const int qb = wbase + 32 * k;
            float2 n2;
            n2.x = rowF;
            n2.y = (float)vals[k];
            __stcs(reinterpret_cast<float2*>(outF) + qb + lane, n2);
            const float vertF = (float)(vbase + k);
            const int   cb    = 3 * qb;
            #pragma unroll
            for (int s = 0; s < 3; s++) {
                const float cv = (comp_[s] == 0) ? rowF
                               : (comp_[s] == 1) ? vertF
                                                 : eF_[s];
                __stcs(colsF + cb + s * 32 + lane, cv);
            }
        }
        return;
    }

    // ===== SPARSE PATH =====
    #pragma unroll
    for (int k = 0; k < ITERS; k++) {
        const int i     = wElemBase + 32 * k + lane;
        const unsigned m = masks[k];
        const int rank  = __popc(m & below);
        const int pexcl = wbase + rank;
        const bool ok   = (m >> lane) & 1u;
        if (i < total) {
            const int q    = ok ? pexcl : (nvalid + (i - pexcl));
            const int row  = i >> 16;
            const int vert = (i >> 5) & 2047;
            const int reg  = i & 31;
            const int v    = vals[k];
            if (LAYOUT == 0) {
                float2 n2;
                n2.x = ok ? (float)row : -1.0f;
                n2.y = ok ? (float)v   : -1.0f;
                __stcs(reinterpret_cast<float2*>(outF) + q, n2);
                float* cp = colsF + 3LL * q;
                __stcs(cp + 0, ok ? (float)row  : -1.0f);
                __stcs(cp + 1, ok ? (float)vert : -1.0f);
                __stcs(cp + 2, ok ? (float)reg  : -1.0f);
            } else if (LAYOUT == 1) {
                long long* out  = (long long*)outv;
                long long* cols = out + 2LL * (long long)total;
                longlong2 n2;
                n2.x = ok ? (long long)row : -1LL;
                n2.y = ok ? (long long)v   : -1LL;
                reinterpret_cast<longlong2*>(out)[q] = n2;
                long long* cp = cols + 3LL * q;
                cp[0] = ok ? (long long)row  : -1LL;
                cp[1] = ok ? (long long)vert : -1LL;
                cp[2] = ok ? (long long)reg  : -1LL;
            } else {
                int* out = (int*)outv;
                int2 n2;
                n2.x = ok ? row : -1;
                n2.y = ok ? v   : -1;
                reinterpret_cast<int2*>(out)[q] = n2;
                long long* cols = (long long*)((char*)outv + 8LL * (long long)total);
                long long* cp = cols + 3LL * q;
                cp[0] = ok ? (long long)row  : -1LL;
                cp[1] = ok ? (long long)vert : -1LL;
                cp[2] = ok ? (long long)reg  : -1LL;
            }
        }
        wbase += __popc(m);
    }
}

extern "C" void kernel_launch(void* const* d_in, const int* in_sizes, int n_in,
                              void* d_out, int out_size) {
    const int* map        = (const int*)d_in[0];
    const int  total      = in_sizes[0];                       // 8388608
    const int  nblocks    = (total + CHUNK - 1) / CHUNK;       // 2048
    const int  cnt_blocks = (total + CNT_CHUNK - 1) / CNT_CHUNK; // 1024

    count_kernel<<<cnt_blocks, CNT_THREADS>>>(map, total, nblocks);

    const long long T = total;
    if ((long long)out_size == 5 * T) {
        scatter_kernel<0><<<nblocks, SC_THREADS>>>(map, d_out, total, nblocks);
    } else if ((long long)out_size == 8 * T) {
        scatter_kernel<2><<<nblocks, SC_THREADS>>>(map, d_out, total, nblocks);
    } else {
        scatter_kernel<1><<<nblocks, SC_THREADS>>>(map, d_out, total, nblocks);
    }
}

// round 16
// speedup vs baseline: 1.4206x; 1.0483x over previous
#include <cuda_runtime.h>
#include <stdint.h>

// Graph2Col: stable stream compaction. 2-kernel: count -> scatter(+inline scan).
// Input : mapping [128, 2048, 32] int32, -1 = empty. total = 8388608.
// Output float32 buffer of 5*total elements:
//   [0, 2*total)        nodes [total,2] : (row, value)      or (-1,-1)
//   [2*total, 5*total)  cols  [total,3] : (row, vert, reg)  or (-1,-1,-1)

#define CHUNK      4096                  // scatter tile
#define SC_THREADS 256
#define SC_WARPS   (SC_THREADS / 32)     // 8
#define WELEMS     (CHUNK / SC_WARPS)    // 512 elements per scatter warp
#define ITERS      (WELEMS / 32)         // 16

#define CNT_CHUNK   8192                 // count tile (2 scatter tiles)
#define CNT_THREADS 256
#define CNT_WARPS   (CNT_THREADS / 32)   // 8
#define CNT_WELEMS  (CNT_CHUNK / CNT_WARPS) // 1024 elems/warp -> 8 int4/lane

#define MAX_BLOCKS 8192

__device__ int g_blk_cnt[MAX_BLOCKS];

__global__ void __launch_bounds__(CNT_THREADS)
count_kernel(const int* __restrict__ map, int total, int sc_blocks) {
    const int blk  = blockIdx.x;
    const int lane = threadIdx.x & 31;
    const int wid  = threadIdx.x >> 5;
    const int wElemBase = blk * CNT_CHUNK + wid * CNT_WELEMS;
    int c = 0;
    if (wElemBase + CNT_WELEMS <= total) {
        const int4* p4 = reinterpret_cast<const int4*>(map) + (wElemBase >> 2);
        int4 r[8];
        #pragma unroll
        for (int k = 0; k < 8; k++) r[k] = __ldg(p4 + 32 * k + lane);
        #pragma unroll
        for (int k = 0; k < 8; k++)
            c += (r[k].x != -1) + (r[k].y != -1) + (r[k].z != -1) + (r[k].w != -1);
    } else {
        for (int k = 0; k < CNT_WELEMS / 32; k++) {
            const int i = wElemBase + 32 * k + lane;
            if (i < total) c += (__ldg(map + i) != -1);
        }
    }
    #pragma unroll
    for (int o = 16; o; o >>= 1) c += __shfl_down_sync(0xffffffffu, c, o);
    __shared__ int ws[CNT_WARPS];
    if (lane == 0) ws[wid] = c;
    __syncthreads();
    // publish two 4096-chunk sub-counts: warps 0-3 and warps 4-7
    if (threadIdx.x < 2) {
        int s = 0;
        #pragma unroll
        for (int w = 0; w < 4; w++) s += ws[threadIdx.x * 4 + w];
        const int sc = blk * 2 + threadIdx.x;
        if (sc < sc_blocks) g_blk_cnt[sc] = s;
    }
}

// LAYOUT 0: float32 (confirmed). 1: int64. 2: int32 nodes + int64 cols.
template <int LAYOUT>
__global__ void __launch_bounds__(SC_THREADS, 6)
scatter_kernel(const int* __restrict__ map, void* __restrict__ outv,
               int total, int nblocks) {
    const int blk  = blockIdx.x;
    const int tid  = threadIdx.x;
    const int lane = tid & 31;
    const int wid  = tid >> 5;
    const int wElemBase = blk * CHUNK + wid * WELEMS;
    const unsigned below = (1u << lane) - 1u;

    // ---- pass 1: warp-strided map loads, keep ONLY the ballot masks ----
    unsigned masks[ITERS];
    int c = 0;
    unsigned allAnd = 0xffffffffu;
    #pragma unroll
    for (int k = 0; k < ITERS; k++) {
        const int i = wElemBase + 32 * k + lane;
        const int v = (i < total) ? __ldg(map + i) : -1;
        const bool ok = (i < total) && (v != -1);
        masks[k] = __ballot_sync(0xffffffffu, ok);
        allAnd &= masks[k];
        c += __popc(masks[k]);   // warp-uniform
    }

    // ---- inline scan: per-block excl prefix + grand total over g_blk_cnt ----
    int exclPart = 0, totPart = 0;
    {
        const int j = tid * 8;
        if (j + 8 <= nblocks) {
            const int4 a = __ldg(reinterpret_cast<const int4*>(g_blk_cnt + j));
            const int4 b = __ldg(reinterpret_cast<const int4*>(g_blk_cnt + j + 4));
            totPart = a.x + a.y + a.z + a.w + b.x + b.y + b.z + b.w;
            if (j + 8 <= blk) {
                exclPart = totPart;
            } else if (j < blk) {
                exclPart  = (j + 0 < blk) ? a.x : 0;
                exclPart += (j + 1 < blk) ? a.y : 0;
                exclPart += (j + 2 < blk) ? a.z : 0;
                exclPart += (j + 3 < blk) ? a.w : 0;
                exclPart += (j + 4 < blk) ? b.x : 0;
                exclPart += (j + 5 < blk) ? b.y : 0;
                exclPart += (j + 6 < blk) ? b.z : 0;
                exclPart += (j + 7 < blk) ? b.w : 0;
            }
        } else {
            for (int u = 0; u < 8; u++) {
                const int jj = j + u;
                const int cv = (jj < nblocks) ? g_blk_cnt[jj] : 0;
                totPart += cv;
                exclPart += (jj < blk) ? cv : 0;
            }
        }
    }
    #pragma unroll
    for (int o = 16; o; o >>= 1) {
        exclPart += __shfl_down_sync(0xffffffffu, exclPart, o);
        totPart  += __shfl_down_sync(0xffffffffu, totPart,  o);
    }

    __shared__ int wsum[SC_WARPS];
    __shared__ int s_ex[SC_WARPS];
    __shared__ int s_to[SC_WARPS];
    if (lane == 0) { wsum[wid] = c; s_ex[wid] = exclPart; s_to[wid] = totPart; }
    __syncthreads();

    int wpref = 0, excl = 0, nvalid = 0;
    #pragma unroll
    for (int w = 0; w < SC_WARPS; w++) {
        wpref  += (w < wid) ? wsum[w] : 0;
        excl   += s_ex[w];
        nvalid += s_to[w];
    }
    int wbase = excl + wpref;

    float* const outF  = (float*)outv;
    float* const colsF = outF + 2LL * (long long)total;

    if (LAYOUT == 0 && allAnd == 0xffffffffu && wElemBase + WELEMS <= total) {
        // ===== DENSE WHOLE-WARP PATH (~78%): branchless, coalesced =====
        const float rowF  = (float)(wElemBase >> 16);
        const int   vbase = (wElemBase >> 5) & 2047;
        int   comp_[3];
        float eF_[3];
        #pragma unroll
        for (int s = 0; s < 3; s++) {
            const int j = s * 32 + lane;
            const int e = (j * 21846) >> 16;   // j / 3
            comp_[s] = j - 3 * e;              // j % 3
            eF_[s]   = (float)e;               // reg = e for 32-aligned block
        }
        #pragma unroll
        for (int k = 0; k < ITERS; k++) {
            const int qb = wbase + 32 * k;
            // reload value: L1 hit (line fetched in pass 1)
            const int v = __ldg(map + wElemBase + 32 * k + lane);
            float2 n2;
            n2.x = rowF;
            n2.y = (float)v;
            __stcs(reinterpret_cast<float2*>(outF) + qb + lane, n2);
            const float vertF = (float)(vbase + k);
            const int   cb    = 3 * qb;
            #pragma unroll
            for (int s = 0; s < 3; s++) {
                const float cv = (comp_[s] == 0) ? rowF
                               : (comp_[s] == 1) ? vertF
                                                 : eF_[s];
                __stcs(colsF + cb + s * 32 + lane, cv);
            }
        }
        return;
    }

    // ===== SPARSE PATH =====
    #pragma unroll
    for (int k = 0; k < ITERS; k++) {
        const int i     = wElemBase + 32 * k + lane;
        const unsigned m = masks[k];
        const int rank  = __popc(m & below);
        const int pexcl = wbase + rank;
        const bool ok   = (m >> lane) & 1u;
        if (i < total) {
            const int v    = __ldg(map + i);   // L1 hit
            const int q    = ok ? pexcl : (nvalid + (i - pexcl));
            const int row  = i >> 16;
            const int vert = (i >> 5) & 2047;
            const int reg  = i & 31;
            if (LAYOUT == 0) {
                float2 n2;
                n2.x = ok ? (float)row : -1.0f;
                n2.y = ok ? (float)v   : -1.0f;
                __stcs(reinterpret_cast<float2*>(outF) + q, n2);
                float* cp = colsF + 3LL * q;
                __stcs(cp + 0, ok ? (float)row  : -1.0f);
                __stcs(cp + 1, ok ? (float)vert : -1.0f);
                __stcs(cp + 2, ok ? (float)reg  : -1.0f);
            } else if (LAYOUT == 1) {
                long long* out  = (long long*)outv;
                long long* cols = out + 2LL * (long long)total;
                longlong2 n2;
                n2.x = ok ? (long long)row : -1LL;
                n2.y = ok ? (long long)v   : -1LL;
                reinterpret_cast<longlong2*>(out)[q] = n2;
                long long* cp = cols + 3LL * q;
                cp[0] = ok ? (long long)row  : -1LL;
                cp[1] = ok ? (long long)vert : -1LL;
                cp[2] = ok ? (long long)reg  : -1LL;
            } else {
                int* out = (int*)outv;
                int2 n2;
                n2.x = ok ? row : -1;
                n2.y = ok ? v   : -1;
                reinterpret_cast<int2*>(out)[q] = n2;
                long long* cols = (long long*)((char*)outv + 8LL * (long long)total);
                long long* cp = cols + 3LL * q;
                cp[0] = ok ? (long long)row  : -1LL;
                cp[1] = ok ? (long long)vert : -1LL;
                cp[2] = ok ? (long long)reg  : -1LL;
            }
        }
        wbase += __popc(m);
    }
}

extern "C" void kernel_launch(void* const* d_in, const int* in_sizes, int n_in,
                              void* d_out, int out_size) {
    const int* map        = (const int*)d_in[0];
    const int  total      = in_sizes[0];                       // 8388608
    const int  nblocks    = (total + CHUNK - 1) / CHUNK;       // 2048
    const int  cnt_blocks = (total + CNT_CHUNK - 1) / CNT_CHUNK; // 1024

    count_kernel<<<cnt_blocks, CNT_THREADS>>>(map, total, nblocks);

    const long long T = total;
    if ((long long)out_size == 5 * T) {
        scatter_kernel<0><<<nblocks, SC_THREADS>>>(map, d_out, total, nblocks);
    } else if ((long long)out_size == 8 * T) {
        scatter_kernel<2><<<nblocks, SC_THREADS>>>(map, d_out, total, nblocks);
    } else {
        scatter_kernel<1><<<nblocks, SC_THREADS>>>(map, d_out, total, nblocks);
    }
}